// round 16
// baseline (speedup 1.0000x reference)
#include <cuda_runtime.h>
#include <cstdint>

#define DD      512
#define HK      2048
#define NB      1024
#define LSLOTS  50
#define KSW     16           // split-K for W gemm
#define NBLK    256          // total blocks (4 supergroups x 64)
#define GRP     64           // blocks per supergroup
#define BD4     (NB * DD / 4)            // 131072 float4 per L-slot

// Scratch (static device globals — no allocation)
__device__ float g_Wpart[KSW * DD * DD];     // split-K partials of Wt[j,a] (16 MB)
__device__ float g_W[DD * DD];               // Wt[j][a] = (wv@wo)[a][j]
__device__ float g_c[DD];                    // bv@wo + bo

// per-supergroup monotone sync counters: [phase][J]
__device__ unsigned g_sync[2 * 4];

__device__ __forceinline__ void group_sync(int J, int phase) {
    __syncthreads();
    if (threadIdx.x == 0) {
        __threadfence();
        unsigned* c = &g_sync[phase * 4 + J];
        unsigned old = atomicAdd(c, 1u);
        unsigned target = (old / GRP + 1u) * GRP;
        while (*(volatile unsigned*)c < target) { __nanosleep(32); }
        __threadfence();
    }
    __syncthreads();
}

// ---------------------------------------------------------------------------
// helpers
// ---------------------------------------------------------------------------
__device__ __forceinline__ void mma8(float* d, const uint32_t* a, const uint32_t* b) {
    asm volatile(
        "mma.sync.aligned.m16n8k8.row.col.f32.tf32.tf32.f32 "
        "{%0,%1,%2,%3}, {%4,%5,%6,%7}, {%8,%9}, {%0,%1,%2,%3};"
        : "+f"(d[0]), "+f"(d[1]), "+f"(d[2]), "+f"(d[3])
        : "r"(a[0]), "r"(a[1]), "r"(a[2]), "r"(a[3]), "r"(b[0]), "r"(b[1]));
}
// ldmatrix x4: four 8x8 b16 matrices (fp32 words viewed as b16 pairs).
__device__ __forceinline__ void ldsm4(uint32_t* r, uint32_t addr) {
    asm volatile("ldmatrix.sync.aligned.m8n8.x4.shared.b16 {%0,%1,%2,%3}, [%4];"
                 : "=r"(r[0]), "=r"(r[1]), "=r"(r[2]), "=r"(r[3]) : "r"(addr));
}
// cp.async 16B (L2-only path)
__device__ __forceinline__ void cpasync16(uint32_t saddr, const void* g) {
    asm volatile("cp.async.cg.shared.global [%0], [%1], 16;"
                 :: "r"(saddr), "l"(g) : "memory");
}
#define CP_COMMIT() asm volatile("cp.async.commit_group;" ::: "memory")
#define CP_WAIT1()  asm volatile("cp.async.wait_group 1;" ::: "memory")
#define CP_WAIT0()  asm volatile("cp.async.wait_group 0;" ::: "memory")

// ---------------------------------------------------------------------------
// P0 GEMM: Wt partial tile 128x128, Kc=32 stages, cp.async 3-deep pipeline.
// A (wo, k-major ATR) scalar LDS; B (wv, n-major) via ldmatrix.
// Values staged as raw fp32; tf32 mma truncates mantissa in HW.
// ---------------------------------------------------------------------------
#define ASZ    4608          // 32*132 ATR A region (use 4224) padded
#define BSZ    4608          // 128*36
#define STAGE  (ASZ + BSZ)   // 9216 words = 36 KB
#define SMEM_WORDS (3 * STAGE)           // 108 KB (3-stage ring)
#define SMEM_BYTES (SMEM_WORDS * 4)

template<int LDA, int LDB, int MTOT, int NTOT, int KCHUNK>
__device__ __forceinline__ void gemm_w_dev(const float* __restrict__ Ag,
                                           const float* __restrict__ Bg,
                                           float* __restrict__ C,
                                           uint32_t* smem,
                                           int bx, int by, int bz) {
    const int t = threadIdx.x;
    const uint32_t sbase = (uint32_t)__cvta_generic_to_shared(smem);
    const int nBase = bx * 128;
    const int mBase = by * 128;
    const int kb    = bz * KCHUNK;

    const bool isA = (t < 128);
    const int tt = t & 127;
    const int rr = tt >> 3;
    const int fc = tt & 7;
    const int jq = tt & 31;
    const int kr = tt >> 5;

    constexpr int NS = KCHUNK / 32;     // 4

    const int w = t >> 5, lane = t & 31;
    const int moff = (w & 3) * 32;
    const int noff = (w >> 2) * 64;
    const int g = lane >> 2, q = lane & 3;

    // B-type ldmatrix lane address (byte units)
    const uint32_t sB0 = sbase +
        (ASZ + (uint32_t)(noff + ((lane >> 4) & 1) * 8 + (lane & 7)) * 36
             + ((lane >> 3) & 1) * 4) * 4;

    float acc[2][8][4];
#pragma unroll
    for (int mt = 0; mt < 2; mt++)
#pragma unroll
        for (int nt = 0; nt < 8; nt++)
#pragma unroll
            for (int r = 0; r < 4; r++) acc[mt][nt][r] = 0.0f;

#define ISSUE(s)                                                                \
    {                                                                           \
        const int buf_ = (s) % 3;                                               \
        if (isA) {                                                              \
            _Pragma("unroll")                                                   \
            for (int i = 0; i < 8; ++i)                                         \
                cpasync16(sbase + (uint32_t)(buf_ * STAGE + (kr + 4*i) * 132    \
                                             + jq * 4) * 4,                     \
                          &Ag[(size_t)(kb + (s)*32 + kr + 4*i) * LDA            \
                              + mBase + jq * 4]);                               \
        } else {                                                                \
            _Pragma("unroll")                                                   \
            for (int i = 0; i < 8; ++i)                                         \
                cpasync16(sbase + (uint32_t)(buf_ * STAGE + ASZ                 \
                                             + (rr + 16*i) * 36 + fc * 4) * 4,  \
                          &Bg[(size_t)(nBase + rr + 16*i) * LDB                 \
                              + kb + (s)*32 + fc * 4]);                         \
        }                                                                       \
    }

    ISSUE(0); CP_COMMIT();
    ISSUE(1); CP_COMMIT();

    for (int s = 0; s < NS; ++s) {
        CP_WAIT1();
        __syncthreads();
        const int buf = s % 3;
        const uint32_t* As = smem + buf * STAGE;
        const uint32_t bBs = sB0 + (uint32_t)buf * STAGE * 4;
#pragma unroll
        for (int k0 = 0; k0 < 32; k0 += 8) {
            uint32_t af[2][4];
#pragma unroll
            for (int mt = 0; mt < 2; mt++) {
                const int m0 = moff + mt * 16 + g;
                af[mt][0] = As[(k0 + q) * 132 + m0];
                af[mt][1] = As[(k0 + q) * 132 + m0 + 8];
                af[mt][2] = As[(k0 + q + 4) * 132 + m0];
                af[mt][3] = As[(k0 + q + 4) * 132 + m0 + 8];
            }
            uint32_t bf[8][2];
#pragma unroll
            for (int p = 0; p < 4; p++) {
                uint32_t r[4];
                ldsm4(r, bBs + (uint32_t)(p * 16 * 36 + k0) * 4);
                bf[2 * p][0] = r[0];     bf[2 * p][1] = r[1];
                bf[2 * p + 1][0] = r[2]; bf[2 * p + 1][1] = r[3];
            }
#pragma unroll
            for (int mt = 0; mt < 2; mt++)
#pragma unroll
                for (int nt = 0; nt < 8; nt++)
                    mma8(acc[mt][nt], af[mt], bf[nt]);
        }
        if (s + 2 < NS) ISSUE(s + 2);
        CP_COMMIT();
    }
    CP_WAIT0();
#undef ISSUE

    float* cz = C + (size_t)bz * MTOT * NTOT;
#pragma unroll
    for (int mt = 0; mt < 2; mt++) {
        const int r0 = mBase + moff + mt * 16 + g;
#pragma unroll
        for (int nt = 0; nt < 8; nt++) {
            const int c0 = nBase + noff + nt * 8 + q * 2;
            float2 v0 = make_float2(acc[mt][nt][0], acc[mt][nt][1]);
            float2 v1 = make_float2(acc[mt][nt][2], acc[mt][nt][3]);
            *(float2*)&cz[(size_t)r0 * NTOT + c0] = v0;
            *(float2*)&cz[(size_t)(r0 + 8) * NTOT + c0] = v1;
        }
    }
}

// ---------------------------------------------------------------------------
// Mega-kernel, 256 blocks = 4 supergroups x 64, 2 blocks/SM.
// Supergroup J owns j-strip [128J, 128J+128) end-to-end:
//   P0 (4 a-tiles x 16 k-slices) | group sync | P1 reduce strip + bias |
//   group sync | P2' 64x32 temp tile (K=512, cp.async pipeline) -> smem ->
//   stream 50 L-slots.
// ---------------------------------------------------------------------------
__global__ __launch_bounds__(256, 2) void k_all(const float* __restrict__ wo,
                                                const float* __restrict__ wv,
                                                const float* __restrict__ hid,
                                                const float* __restrict__ bv,
                                                const float* __restrict__ bo,
                                                const float* __restrict__ wsc,
                                                const float4* __restrict__ mom,
                                                float4* __restrict__ out) {
    extern __shared__ uint32_t smem[];
    __shared__ float sred[8];
    const int b = blockIdx.x;
    const int t = threadIdx.x;
    const int J = b >> 6;           // supergroup 0..3 (j-strip 128J..)
    const int u = b & 63;           // member within supergroup

    // ---- P0: Wt partials for rows [128J, 128J+128)
    gemm_w_dev<DD, HK, DD, DD, HK / KSW>(wo, wv, g_Wpart, smem,
                                         u & 3, J, u >> 2);
    group_sync(J, 0);

    // ---- P1a: reduce this strip's W partials (16384 float4 / 64 blocks)
    {
        const float4* p = (const float4*)g_Wpart;
        int i = J * 16384 + u * 256 + t;
        float4 s = p[i];
#pragma unroll
        for (int k = 1; k < KSW; k++) {
            float4 v = p[k * (DD * DD / 4) + i];
            s.x += v.x; s.y += v.y; s.z += v.z; s.w += v.w;
        }
        ((float4*)g_W)[i] = s;
    }
    // ---- P1b: bias c[j] for this strip (2 j's per block)
    {
        const int jloc = t >> 7;               // 0..1
        const int j = J * 128 + u * 2 + jloc;
        const int tk = t & 127;
        float acc = 0.0f;
        const int k0 = tk * 16;
        for (int k = k0; k < k0 + 16; k++)
            acc += bv[k] * wo[(size_t)k * DD + j];
#pragma unroll
        for (int off = 16; off > 0; off >>= 1)
            acc += __shfl_down_sync(0xFFFFFFFFu, acc, off);
        if ((t & 31) == 0) sred[t >> 5] = acc;
        __syncthreads();
        if (t < 2)
            g_c[J * 128 + u * 2 + t] = sred[4 * t] + sred[4 * t + 1]
                                     + sred[4 * t + 2] + sred[4 * t + 3]
                                     + bo[J * 128 + u * 2 + t];
    }
    group_sync(J, 1);

    // ---- P2': temp tile (64 b-rows x 32 j-cols, full K=512), then stream.
    {
        const uint32_t sbase = (uint32_t)__cvta_generic_to_shared(smem);
        const int mBase = (u & 15) * 64;
        const int nBase = J * 128 + (u >> 4) * 32;
        const int kq = t & 15, r0 = t >> 4;      // loader map
        const int w = t >> 5, lane = t & 31;
        const int moff = (w & 3) * 16;
        const int noff = (w >> 2) * 16;
        const int g = lane >> 2, q = lane & 3;

        constexpr int APITCH = 68;
        constexpr int BOFF = 64 * APITCH;                 // 4352
        constexpr int P2STAGE = BOFF + 32 * APITCH;       // 6528

        // ldmatrix lane addresses (byte units)
        const uint32_t aA0 = sbase +
            ((uint32_t)(moff + ((lane >> 3) & 1) * 8 + (lane & 7)) * APITCH
             + ((lane >> 4) & 1) * 4) * 4;
        const uint32_t bB0 = sbase +
            ((uint32_t)BOFF
             + (uint32_t)(noff + ((lane >> 4) & 1) * 8 + (lane & 7)) * APITCH
             + ((lane >> 3) & 1) * 4) * 4;

        float acc[2][4];
#pragma unroll
        for (int nt = 0; nt < 2; nt++)
#pragma unroll
            for (int r = 0; r < 4; r++) acc[nt][r] = 0.0f;

#define ISSUE2(s)                                                               \
        {                                                                       \
            const int buf_ = (s) % 3;                                           \
            const uint32_t dst_ = sbase + (uint32_t)(buf_ * P2STAGE) * 4;       \
            _Pragma("unroll")                                                   \
            for (int i = 0; i < 4; ++i)                                         \
                cpasync16(dst_ + (uint32_t)((r0 + 16*i) * APITCH + kq * 4) * 4, \
                          &hid[(size_t)(mBase + r0 + 16*i) * DD                 \
                               + (s)*64 + kq * 4]);                             \
            _Pragma("unroll")                                                   \
            for (int i = 0; i < 2; ++i)                                         \
                cpasync16(dst_ + (uint32_t)(BOFF + (r0 + 16*i) * APITCH         \
                                            + kq * 4) * 4,                      \
                          &g_W[(size_t)(nBase + r0 + 16*i) * DD                 \
                               + (s)*64 + kq * 4]);                             \
        }

        ISSUE2(0); CP_COMMIT();
        ISSUE2(1); CP_COMMIT();

        for (int s = 0; s < 8; ++s) {
            CP_WAIT1();
            __syncthreads();
            const int buf = s % 3;
            const uint32_t aAs = aA0 + (uint32_t)buf * P2STAGE * 4;
            const uint32_t bBs = bB0 + (uint32_t)buf * P2STAGE * 4;
#pragma unroll
            for (int k0 = 0; k0 < 64; k0 += 8) {
                uint32_t af[4];
                ldsm4(af, aAs + (uint32_t)k0 * 4);
                uint32_t rbf[4];
                ldsm4(rbf, bBs + (uint32_t)k0 * 4);
                uint32_t bf[2][2];
                bf[0][0] = rbf[0]; bf[0][1] = rbf[1];
                bf[1][0] = rbf[2]; bf[1][1] = rbf[3];
                mma8(acc[0], af, bf[0]);
                mma8(acc[1], af, bf[1]);
            }
            if (s + 2 < 8) ISSUE2(s + 2);
            CP_COMMIT();
        }
        CP_WAIT0();
#undef ISSUE2
        __syncthreads();

        // epilogue: temp tile (64x32) with bias+scale into smem [64][36]
        float* ts = (float*)smem;
        const float sc = 3.0f * wsc[0];
#pragma unroll
        for (int nt = 0; nt < 2; nt++) {
            const int c0 = noff + nt * 8 + q * 2;
            const float cv0 = g_c[nBase + c0];
            const float cv1 = g_c[nBase + c0 + 1];
            ts[(moff + g) * 36 + c0]     = sc * (acc[nt][0] + cv0);
            ts[(moff + g) * 36 + c0 + 1] = sc * (acc[nt][1] + cv1);
            ts[(moff + g + 8) * 36 + c0]     = sc * (acc[nt][2] + cv0);
            ts[(moff + g + 8) * 36 + c0 + 1] = sc * (acc[nt][3] + cv1);
        }
        __syncthreads();

        // stream: out[l, mBase..+64, nBase..+32] for l = 0..49
        const int ri = t >> 3;          // 0..31 (rows ri, ri+32)
        const int jq2 = t & 7;          // float4 within 32-col row
        float4 T0 = *(const float4*)&ts[ri * 36 + jq2 * 4];
        float4 T1 = *(const float4*)&ts[(ri + 32) * 36 + jq2 * 4];
        const int nb4 = nBase >> 2;
        const int base0 = (mBase + ri) * (DD / 4) + nb4 + jq2;
        const int base1 = (mBase + ri + 32) * (DD / 4) + nb4 + jq2;

#pragma unroll 1
        for (int l = 0; l < LSLOTS; l += 5) {
            float4 m[10];
            int idx[10];
#pragma unroll
            for (int v = 0; v < 5; ++v) {
                idx[2 * v]     = (l + v) * BD4 + base0;
                idx[2 * v + 1] = (l + v) * BD4 + base1;
                m[2 * v]     = __ldcs(&mom[idx[2 * v]]);
                m[2 * v + 1] = __ldcs(&mom[idx[2 * v + 1]]);
            }
#pragma unroll
            for (int v = 0; v < 5; ++v) {
                m[2*v].x += T0.x; m[2*v].y += T0.y; m[2*v].z += T0.z; m[2*v].w += T0.w;
                m[2*v+1].x += T1.x; m[2*v+1].y += T1.y; m[2*v+1].z += T1.z; m[2*v+1].w += T1.w;
                __stcs(&out[idx[2 * v]], m[2 * v]);
                __stcs(&out[idx[2 * v + 1]], m[2 * v + 1]);
            }
        }
    }
}

// ---------------------------------------------------------------------------
// Launch. Inputs (metadata order):
// 0 momery, 1 hid, 2 text_polarity, 3 attribute_polarity, 4 w,
// 5 p_w1, 6 p_b1, 7 p_w2, 8 p_b2, 9 wq, 10 bq, 11 wk, 12 bk,
// 13 wv, 14 bv, 15 wo, 16 bo
// ---------------------------------------------------------------------------
extern "C" void kernel_launch(void* const* d_in, const int* in_sizes, int n_in,
                              void* d_out, int out_size) {
    const float* momery = (const float*)d_in[0];
    const float* hid    = (const float*)d_in[1];
    const float* w      = (const float*)d_in[4];
    const float* wv     = (const float*)d_in[13];
    const float* bv     = (const float*)d_in[14];
    const float* wo     = (const float*)d_in[15];
    const float* bo     = (const float*)d_in[16];
    float* out = (float*)d_out;

    cudaFuncSetAttribute(k_all, cudaFuncAttributeMaxDynamicSharedMemorySize,
                         SMEM_BYTES);

    k_all<<<NBLK, 256, SMEM_BYTES>>>(wo, wv, hid, bv, bo, w,
                                     (const float4*)momery, (float4*)out);
}